// round 16
// baseline (speedup 1.0000x reference)
#include <cuda_runtime.h>
#include <cuda_fp16.h>
#include <math.h>
#include <stdint.h>

#define BATCHN 4
#define SEQ    2048
#define EMBD   512
#define HEADS  8
#define HE     4096            // HEADS * EMBD
#define MROWS  8192            // BATCHN * SEQ

// ---------------------------------------------------------------------------
// Scratch (allocation-free: device globals)
// ---------------------------------------------------------------------------
__device__ __half g_Xh [(size_t)MROWS * EMBD];
__device__ __half g_Qh [(size_t)MROWS * HE];
__device__ __half g_Kh [(size_t)MROWS * HE];
__device__ __half g_Vh [(size_t)MROWS * HE];
__device__ __half g_Ph [(size_t)BATCHN * HEADS * SEQ * SEQ];   // fp16 logits -> probs
__device__ __half g_AOh[(size_t)MROWS * HE];
__device__ __half g_Wqh[(size_t)EMBD * HE];
__device__ __half g_Wkh[(size_t)EMBD * HE];
__device__ __half g_Wvh[(size_t)EMBD * HE];
__device__ __half g_Woh[(size_t)HE * EMBD];

// ---------------------------------------------------------------------------
// helpers
// ---------------------------------------------------------------------------
__device__ __forceinline__ uint32_t smem_u32(const void* p) {
    uint32_t a;
    asm("{ .reg .u64 t; cvta.to.shared.u64 t, %1; cvt.u32.u64 %0, t; }" : "=r"(a) : "l"(p));
    return a;
}
__device__ __forceinline__ void mma_f16(float& c0, float& c1, float& c2, float& c3,
                                        uint32_t a0, uint32_t a1, uint32_t a2, uint32_t a3,
                                        uint32_t b0, uint32_t b1) {
    asm volatile("mma.sync.aligned.m16n8k16.row.col.f32.f16.f16.f32 "
                 "{%0,%1,%2,%3},{%4,%5,%6,%7},{%8,%9},{%0,%1,%2,%3};"
                 : "+f"(c0), "+f"(c1), "+f"(c2), "+f"(c3)
                 : "r"(a0), "r"(a1), "r"(a2), "r"(a3), "r"(b0), "r"(b1));
}
__device__ __forceinline__ void ldm_x4(uint32_t& r0, uint32_t& r1, uint32_t& r2,
                                       uint32_t& r3, uint32_t addr) {
    asm volatile("ldmatrix.sync.aligned.m8n8.x4.shared.b16 {%0,%1,%2,%3}, [%4];"
                 : "=r"(r0), "=r"(r1), "=r"(r2), "=r"(r3) : "r"(addr));
}
__device__ __forceinline__ void ldm_x4_t(uint32_t& r0, uint32_t& r1, uint32_t& r2,
                                         uint32_t& r3, uint32_t addr) {
    asm volatile("ldmatrix.sync.aligned.m8n8.x4.trans.shared.b16 {%0,%1,%2,%3}, [%4];"
                 : "=r"(r0), "=r"(r1), "=r"(r2), "=r"(r3) : "r"(addr));
}
#define CP_ASYNC16(s, g)  asm volatile("cp.async.cg.shared.global [%0], [%1], 16;" :: "r"(s), "l"(g) : "memory")
#define CP_COMMIT()       asm volatile("cp.async.commit_group;" ::: "memory")
#define CP_WAIT1()        asm volatile("cp.async.wait_group 1;" ::: "memory")

// ---------------------------------------------------------------------------
// fp16 GEMM, fp32 accum: C[M,N] = alpha * A[M,K] * op(B) (+ bias)
//   TRB=true : B is [N,K] (K-major)  -> C = A B^T   (non-trans ldmatrix)
//   TRB=false: B is [K,N] (N-major)  -> C = A B     (trans ldmatrix)
// CTA 256x128xBK64(halfs), 256 threads (1 CTA/SM), warp grid 4(M)x2(N),
// warp tile 64x64 (4x8 m16n8k16), 3-stage cp.async, cross-iteration
// fragment prefetch, cp.async interleaved into the mma stream.
// ---------------------------------------------------------------------------
#define BM 256
#define BN 128
#define BKH 64                          // halfs per stage-k (four k16 steps)
#define RSH 72                          // A / NT-B padded row stride (halfs)
#define RBH 136                         // NN-B padded row stride (halfs)
#define ATILE_BYTES (BM * RSH * 2)      // 36864
#define NSTAGE 3
#define SMEM_MAX (NSTAGE * (ATILE_BYTES + 128 * RSH * 2))   // 165888 (TRB variant)

template<typename Tout, bool TRB>
__global__ __launch_bounds__(256, 1)
void h_gemm(const __half* __restrict__ Ag, const __half* __restrict__ Bg,
            Tout* __restrict__ Cg, int K,
            long lda, long ldb, long ldc,
            long sAb, long sAh, long sBb, long sBh, long sCb, long sCh,
            int Hdiv, float alpha, const float* __restrict__ bias)
{
    constexpr uint32_t BTILE_BYTES = TRB ? (128 * RSH * 2) : (64 * RBH * 2);
    constexpr uint32_t STAGE_BYTES = ATILE_BYTES + BTILE_BYTES;

    extern __shared__ __half smem[];
    const uint32_t sbase = smem_u32(smem);

    const int tid  = threadIdx.x;
    const int wid  = tid >> 5;
    const int lane = tid & 31;
    const int wm   = wid >> 1;         // 0..3 -> 64-row slab
    const int wn   = wid & 1;          // 0..1 -> 64-col slab
    const int lg   = lane >> 2;        // 0..7
    const int lr   = lane & 3;         // 0..3

    const int zb = blockIdx.z / Hdiv;
    const int zh = blockIdx.z % Hdiv;
    const __half* A = Ag + zb * sAb + zh * sAh;
    const __half* B = Bg + zb * sBb + zh * sBh;
    Tout*         C = Cg + zb * sCb + zh * sCh;

    const int m0 = blockIdx.y * BM;
    const int n0 = blockIdx.x * BN;

    // A ldmatrix base (per-lane byte offset within a stage)
    const int arow = lane & 15;
    const int acol = (lane >> 4) << 3;
    const uint32_t aoff = ((wm * 64 + arow) * RSH + acol) * 2;

    // B ldmatrix base
    uint32_t boff;
    if constexpr (TRB) {
        const int brow = (lane & 7) | ((lane >> 4) << 3);
        const int bcol = ((lane >> 3) & 1) << 3;
        boff = ATILE_BYTES + ((wn * 64 + brow) * RSH + bcol) * 2;
    } else {
        const int krow = (lane & 7) + 8 * ((lane >> 3) & 1);
        const int ncol = wn * 64 + 8 * (lane >> 4);
        boff = ATILE_BYTES + krow * (RBH * 2) + ncol * 2;
    }

    float acc[4][8][4];
#pragma unroll
    for (int i = 0; i < 4; ++i)
#pragma unroll
        for (int j = 0; j < 8; ++j)
#pragma unroll
            for (int l = 0; l < 4; ++l) acc[i][j][l] = 0.f;

    const int NT = K / BKH;

    // one quarter of a stage load (j=0..3): A 2 chunks + B 1 chunk per thread
    auto cp_chunk = [&](int kt, int j) {
        const int ring = kt % NSTAGE;
        const uint32_t base = sbase + ring * STAGE_BYTES;
        const int k0 = kt * BKH;
#pragma unroll
        for (int i = 2 * j; i < 2 * j + 2; ++i) {
            int id = tid + i * 256;
            int row = id >> 3, ch = id & 7;
            CP_ASYNC16(base + row * (RSH * 2) + ch * 16,
                       A + (size_t)(m0 + row) * lda + k0 + ch * 8);
        }
        if constexpr (TRB) {
            int id = tid + j * 256;
            int row = id >> 3, ch = id & 7;
            CP_ASYNC16(base + ATILE_BYTES + row * (RSH * 2) + ch * 16,
                       B + (size_t)(n0 + row) * ldb + k0 + ch * 8);
        } else {
            int id = tid + j * 256;
            int row = id >> 4, ch = id & 15;
            CP_ASYNC16(base + ATILE_BYTES + row * (RBH * 2) + ch * 16,
                       B + (size_t)(k0 + row) * ldb + n0 + ch * 8);
        }
    };

    auto load_stage = [&](int kt) {
#pragma unroll
        for (int j = 0; j < 4; ++j) cp_chunk(kt, j);
        CP_COMMIT();
    };

    // fragment loader: frags for k16-chunk ks (0..3) of the stage at 'stg'
    auto ldm_all = [&](uint32_t stg, int ks, uint32_t af[4][4], uint32_t bf[8][2]) {
#pragma unroll
        for (int mt = 0; mt < 4; ++mt)
            ldm_x4(af[mt][0], af[mt][1], af[mt][2], af[mt][3],
                   stg + aoff + mt * (16 * RSH * 2) + ks * 32);
        if constexpr (TRB) {
#pragma unroll
            for (int np = 0; np < 4; ++np)
                ldm_x4(bf[2 * np][0], bf[2 * np][1], bf[2 * np + 1][0], bf[2 * np + 1][1],
                       stg + boff + np * (16 * RSH * 2) + ks * 32);
        } else {
#pragma unroll
            for (int np = 0; np < 4; ++np)
                ldm_x4_t(bf[2 * np][0], bf[2 * np][1], bf[2 * np + 1][0], bf[2 * np + 1][1],
                         stg + boff + ks * (16 * RBH * 2) + np * 32);
        }
    };

    // one quarter of an mma phase: fixed mt row, all 8 nt (8 HMMA)
    auto mma_quarter = [&](uint32_t af[4][4], uint32_t bf[8][2], int mt) {
#pragma unroll
        for (int nt = 0; nt < 8; ++nt)
            mma_f16(acc[mt][nt][0], acc[mt][nt][1], acc[mt][nt][2], acc[mt][nt][3],
                    af[mt][0], af[mt][1], af[mt][2], af[mt][3],
                    bf[nt][0], bf[nt][1]);
    };

    auto mma_all = [&](uint32_t af[4][4], uint32_t bf[8][2]) {
#pragma unroll
        for (int mt = 0; mt < 4; ++mt) mma_quarter(af, bf, mt);
    };

    load_stage(0); load_stage(1);

    // Prologue: stage 0 complete + published; preload (kt=0, ks=0) frags.
    CP_WAIT1();
    __syncthreads();

    uint32_t afA[4][4], bfA[8][2], afB[4][4], bfB[8][2];
    ldm_all(sbase, 0, afA, bfA);

    for (int kt = 0; kt < NT; ++kt) {
        const uint32_t stg = sbase + (kt % NSTAGE) * STAGE_BYTES;
        const bool doLoad = (kt + 2 < NT);

        // phase ks0 with interleaved cp.async for stage kt+2
        ldm_all(stg, 1, afB, bfB);
        mma_quarter(afA, bfA, 0);  if (doLoad) cp_chunk(kt + 2, 0);
        mma_quarter(afA, bfA, 1);  if (doLoad) cp_chunk(kt + 2, 1);
        mma_quarter(afA, bfA, 2);  if (doLoad) cp_chunk(kt + 2, 2);
        mma_quarter(afA, bfA, 3);  if (doLoad) cp_chunk(kt + 2, 3);
        CP_COMMIT();   // exactly one group per body (keeps wait_group math)

        // phase ks1
        ldm_all(stg, 2, afA, bfA);
        mma_all(afB, bfB);

        // phase ks2
        ldm_all(stg, 3, afB, bfB);
        mma_all(afA, bfA);

        // stage kt+1 complete + published before prefetching from it
        CP_WAIT1();
        __syncthreads();

        // phase ks3 + cross-iteration prefetch of (kt+1, ks0)
        const int ktn = (kt + 1 < NT) ? kt + 1 : kt;
        ldm_all(sbase + (ktn % NSTAGE) * STAGE_BYTES, 0, afA, bfA);
        mma_all(afB, bfB);
    }

    // epilogue
#pragma unroll
    for (int mt = 0; mt < 4; ++mt) {
#pragma unroll
        for (int nt = 0; nt < 8; ++nt) {
            const int r0 = m0 + wm * 64 + mt * 16 + lg;
            const int c0 = n0 + wn * 64 + nt * 8 + 2 * lr;
            float b0v = 0.f, b1v = 0.f;
            if (bias) { b0v = bias[c0]; b1v = bias[c0 + 1]; }
            float v00 = alpha * acc[mt][nt][0] + b0v;
            float v01 = alpha * acc[mt][nt][1] + b1v;
            float v10 = alpha * acc[mt][nt][2] + b0v;
            float v11 = alpha * acc[mt][nt][3] + b1v;
            if constexpr (sizeof(Tout) == 4) {
                *(float2*)((float*)C + (size_t)r0 * ldc + c0)       = make_float2(v00, v01);
                *(float2*)((float*)C + (size_t)(r0 + 8) * ldc + c0) = make_float2(v10, v11);
            } else {
                *(__half2*)((__half*)C + (size_t)r0 * ldc + c0)       = __float22half2_rn(make_float2(v00, v01));
                *(__half2*)((__half*)C + (size_t)(r0 + 8) * ldc + c0) = __float22half2_rn(make_float2(v10, v11));
            }
        }
    }
}

// fp32 -> fp16 elementwise (vectorized x2)
__global__ void conv_h(const float* __restrict__ in, __half* __restrict__ out, int n2)
{
    int i = blockIdx.x * blockDim.x + threadIdx.x;
    if (i < n2) {
        float2 v = *(const float2*)(in + 2 * i);
        *(__half2*)(out + 2 * i) = __float22half2_rn(v);
    }
}

// ---------------------------------------------------------------------------
// Row softmax in place on fp16 logits. 256 thr, 2048 cols.
// ---------------------------------------------------------------------------
__global__ void softmax_rows(__half* __restrict__ P)
{
    __half* q = P + (size_t)blockIdx.x * SEQ;
    const int tid = threadIdx.x;

    float2 v[4];
    float mx = -1e30f;
#pragma unroll
    for (int i = 0; i < 4; ++i) {
        v[i] = __half22float2(*(const __half2*)(q + 2 * tid + 512 * i));
        mx = fmaxf(mx, fmaxf(v[i].x, v[i].y));
    }
    __shared__ float red[256];
    red[tid] = mx; __syncthreads();
    for (int s = 128; s > 0; s >>= 1) { if (tid < s) red[tid] = fmaxf(red[tid], red[tid + s]); __syncthreads(); }
    mx = red[0]; __syncthreads();
    float sum = 0.f;
#pragma unroll
    for (int i = 0; i < 4; ++i) {
        v[i].x = __expf(v[i].x - mx); v[i].y = __expf(v[i].y - mx);
        sum += v[i].x + v[i].y;
    }
    red[tid] = sum; __syncthreads();
    for (int s = 128; s > 0; s >>= 1) { if (tid < s) red[tid] += red[tid + s]; __syncthreads(); }
    const float inv = 1.f / red[0];
#pragma unroll
    for (int i = 0; i < 4; ++i)
        *(__half2*)(q + 2 * tid + 512 * i) =
            __float22half2_rn(make_float2(v[i].x * inv, v[i].y * inv));
}

// ---------------------------------------------------------------------------
// Launch — s1 joins capture at t=0 via evStart (legal fork), then weight
// converts run on s1 (Wq first, per-weight events gate Q/K projections).
// Fork after scores gates the V projection (co-runs with softmax); join
// before AV. All cross-stream edges originate inside the capture.
// ---------------------------------------------------------------------------
extern "C" void kernel_launch(void* const* d_in, const int* in_sizes, int n_in,
                              void* d_out, int out_size)
{
    const float* x  = (const float*)d_in[0];
    const float* Wq = (const float*)d_in[1];
    const float* bq = (const float*)d_in[2];
    const float* Wk = (const float*)d_in[3];
    const float* bk = (const float*)d_in[4];
    const float* Wv = (const float*)d_in[5];
    const float* bv = (const float*)d_in[6];
    const float* Wo = (const float*)d_in[7];
    const float* bo = (const float*)d_in[8];
    float* out = (float*)d_out;

    __half *pXh, *pQh, *pKh, *pVh, *pPh, *pAOh, *pWqh, *pWkh, *pWvh, *pWoh;
    cudaGetSymbolAddress((void**)&pXh,  g_Xh);
    cudaGetSymbolAddress((void**)&pQh,  g_Qh);
    cudaGetSymbolAddress((void**)&pKh,  g_Kh);
    cudaGetSymbolAddress((void**)&pVh,  g_Vh);
    cudaGetSymbolAddress((void**)&pPh,  g_Ph);
    cudaGetSymbolAddress((void**)&pAOh, g_AOh);
    cudaGetSymbolAddress((void**)&pWqh, g_Wqh);
    cudaGetSymbolAddress((void**)&pWkh, g_Wkh);
    cudaGetSymbolAddress((void**)&pWvh, g_Wvh);
    cudaGetSymbolAddress((void**)&pWoh, g_Woh);

    cudaFuncSetAttribute((const void*)h_gemm<__half, false>, cudaFuncAttributeMaxDynamicSharedMemorySize, SMEM_MAX);
    cudaFuncSetAttribute((const void*)h_gemm<__half, true>,  cudaFuncAttributeMaxDynamicSharedMemorySize, SMEM_MAX);
    cudaFuncSetAttribute((const void*)h_gemm<float, false>,  cudaFuncAttributeMaxDynamicSharedMemorySize, SMEM_MAX);

    // Side stream + events (host objects, created once; no device memory).
    static cudaStream_t s1 = nullptr;
    static cudaEvent_t evStart = nullptr, evWq = nullptr, evWk = nullptr,
                       evFork = nullptr, evJoin = nullptr;
    if (s1 == nullptr) {
        cudaStreamCreateWithFlags(&s1, cudaStreamNonBlocking);
        cudaEventCreateWithFlags(&evStart, cudaEventDisableTiming);
        cudaEventCreateWithFlags(&evWq,    cudaEventDisableTiming);
        cudaEventCreateWithFlags(&evWk,    cudaEventDisableTiming);
        cudaEventCreateWithFlags(&evFork,  cudaEventDisableTiming);
        cudaEventCreateWithFlags(&evJoin,  cudaEventDisableTiming);
    }

    const float scale = 1.0f / sqrtf((float)EMBD);

    // t=0: fork s1 into the capture FIRST (all s1 work must descend from the
    // origin stream for the cross-waits below to be legal graph edges).
    cudaEventRecord(evStart, 0);
    cudaStreamWaitEvent(s1, evStart, 0);

    // side stream: weight converts, Wq first (critical), then Wk/Wv/Wo.
    conv_h<<<(EMBD * HE / 2 + 255) / 256, 256, 0, s1>>>(Wq, pWqh, EMBD * HE / 2);
    cudaEventRecord(evWq, s1);
    conv_h<<<(EMBD * HE / 2 + 255) / 256, 256, 0, s1>>>(Wk, pWkh, EMBD * HE / 2);
    cudaEventRecord(evWk, s1);
    conv_h<<<(EMBD * HE / 2 + 255) / 256, 256, 0, s1>>>(Wv, pWvh, EMBD * HE / 2);
    conv_h<<<(HE * EMBD / 2 + 255) / 256, 256, 0, s1>>>(Wo, pWoh, HE * EMBD / 2);

    // main stream: x convert (co-runs with Wq convert).
    conv_h<<<(MROWS * EMBD / 2 + 255) / 256, 256>>>(x, pXh, MROWS * EMBD / 2);

    // 1) Q projection (needs x + Wq)
    cudaStreamWaitEvent(0, evWq, 0);
    {
        dim3 g(HE / BN, MROWS / BM, 1);
        h_gemm<__half, false><<<g, 256, SMEM_MAX>>>(pXh, pWqh, pQh, EMBD, EMBD, HE, HE,
                                                    0, 0, 0, 0, 0, 0, 1, 1.f, bq);
    }

    // 2) K projection (needs Wk)
    cudaStreamWaitEvent(0, evWk, 0);
    {
        dim3 g(HE / BN, MROWS / BM, 1);
        h_gemm<__half, false><<<g, 256, SMEM_MAX>>>(pXh, pWkh, pKh, EMBD, EMBD, HE, HE,
                                                    0, 0, 0, 0, 0, 0, 1, 1.f, bk);
    }

    // 3) logits = scale * Q K^T -> fp16 (NT)
    {
        dim3 g(SEQ / BN, SEQ / BM, BATCHN * HEADS);
        h_gemm<__half, true><<<g, 256, SMEM_MAX>>>(pQh, pKh, pPh, EMBD, HE, HE, SEQ,
                                                   (long)SEQ * HE, (long)EMBD,
                                                   (long)SEQ * HE, (long)EMBD,
                                                   (long)HEADS * SEQ * SEQ, (long)SEQ * SEQ,
                                                   HEADS, scale, nullptr);
    }

    // Fork AFTER scores: V-proj (side) co-runs with softmax (main).
    cudaEventRecord(evFork, 0);
    cudaStreamWaitEvent(s1, evFork, 0);

    // side stream: V projection (Wv converted long ago, same stream s1)
    {
        dim3 g(HE / BN, MROWS / BM, 1);
        h_gemm<__half, false><<<g, 256, SMEM_MAX, s1>>>(pXh, pWvh, pVh, EMBD, EMBD, HE, HE,
                                                        0, 0, 0, 0, 0, 0, 1, 1.f, bv);
    }
    cudaEventRecord(evJoin, s1);

    // main stream: softmax in place (fp16), concurrent with V projection
    softmax_rows<<<BATCHN * HEADS * SEQ, 256>>>(pPh);

    // join before AV
    cudaStreamWaitEvent(0, evJoin, 0);

    // 4) AO = P @ V (NN: B = V [s x emb] per head)
    {
        dim3 g(EMBD / BN, SEQ / BM, BATCHN * HEADS);
        h_gemm<__half, false><<<g, 256, SMEM_MAX>>>(pPh, pVh, pAOh, SEQ, SEQ, HE, HE,
                                                    (long)HEADS * SEQ * SEQ, (long)SEQ * SEQ,
                                                    (long)SEQ * HE, (long)EMBD,
                                                    (long)SEQ * HE, (long)EMBD,
                                                    HEADS, 1.f, nullptr);
    }

    // 5) out = AO @ Wo + bo (NN: B = Wo [4096 x 512])
    {
        dim3 g(EMBD / BN, MROWS / BM, 1);
        h_gemm<float, false><<<g, 256, SMEM_MAX>>>(pAOh, pWoh, out, HE, HE, EMBD, EMBD,
                                                   0, 0, 0, 0, 0, 0, 1, 1.f, bo);
    }
}

// round 17
// speedup vs baseline: 1.0036x; 1.0036x over previous
#include <cuda_runtime.h>
#include <cuda_fp16.h>
#include <math.h>
#include <stdint.h>

#define BATCHN 4
#define SEQ    2048
#define EMBD   512
#define HEADS  8
#define HE     4096            // HEADS * EMBD
#define MROWS  8192            // BATCHN * SEQ

// ---------------------------------------------------------------------------
// Scratch (allocation-free: device globals)
// ---------------------------------------------------------------------------
__device__ __half g_Xh [(size_t)MROWS * EMBD];
__device__ __half g_Qh [(size_t)MROWS * HE];
__device__ __half g_Kh [(size_t)MROWS * HE];
__device__ __half g_Vh [(size_t)MROWS * HE];
__device__ __half g_Ph [(size_t)BATCHN * HEADS * SEQ * SEQ];   // fp16 logits -> probs
__device__ __half g_AOh[(size_t)MROWS * HE];
__device__ __half g_Wqh[(size_t)EMBD * HE];
__device__ __half g_Wkh[(size_t)EMBD * HE];
__device__ __half g_Wvh[(size_t)EMBD * HE];
__device__ __half g_Woh[(size_t)HE * EMBD];

// ---------------------------------------------------------------------------
// helpers
// ---------------------------------------------------------------------------
__device__ __forceinline__ uint32_t smem_u32(const void* p) {
    uint32_t a;
    asm("{ .reg .u64 t; cvta.to.shared.u64 t, %1; cvt.u32.u64 %0, t; }" : "=r"(a) : "l"(p));
    return a;
}
__device__ __forceinline__ void mma_f16(float& c0, float& c1, float& c2, float& c3,
                                        uint32_t a0, uint32_t a1, uint32_t a2, uint32_t a3,
                                        uint32_t b0, uint32_t b1) {
    asm volatile("mma.sync.aligned.m16n8k16.row.col.f32.f16.f16.f32 "
                 "{%0,%1,%2,%3},{%4,%5,%6,%7},{%8,%9},{%0,%1,%2,%3};"
                 : "+f"(c0), "+f"(c1), "+f"(c2), "+f"(c3)
                 : "r"(a0), "r"(a1), "r"(a2), "r"(a3), "r"(b0), "r"(b1));
}
__device__ __forceinline__ void ldm_x4(uint32_t& r0, uint32_t& r1, uint32_t& r2,
                                       uint32_t& r3, uint32_t addr) {
    asm volatile("ldmatrix.sync.aligned.m8n8.x4.shared.b16 {%0,%1,%2,%3}, [%4];"
                 : "=r"(r0), "=r"(r1), "=r"(r2), "=r"(r3) : "r"(addr));
}
__device__ __forceinline__ void ldm_x4_t(uint32_t& r0, uint32_t& r1, uint32_t& r2,
                                         uint32_t& r3, uint32_t addr) {
    asm volatile("ldmatrix.sync.aligned.m8n8.x4.trans.shared.b16 {%0,%1,%2,%3}, [%4];"
                 : "=r"(r0), "=r"(r1), "=r"(r2), "=r"(r3) : "r"(addr));
}
#define CP_ASYNC16(s, g)  asm volatile("cp.async.cg.shared.global [%0], [%1], 16;" :: "r"(s), "l"(g) : "memory")
#define CP_COMMIT()       asm volatile("cp.async.commit_group;" ::: "memory")
#define CP_WAIT1()        asm volatile("cp.async.wait_group 1;" ::: "memory")

// ---------------------------------------------------------------------------
// fp16 GEMM, fp32 accum: C[M,N] = alpha * A[M,K] * op(B) (+ bias)
//   TRB=true : B is [N,K] (K-major)  -> C = A B^T   (non-trans ldmatrix)
//   TRB=false: B is [K,N] (N-major)  -> C = A B     (trans ldmatrix)
// CTA 256x128xBK64(halfs), 256 threads (1 CTA/SM), warp grid 4(M)x2(N),
// warp tile 64x64 (4x8 m16n8k16), 3-stage cp.async, cross-iteration
// fragment prefetch, cp.async interleaved into the mma stream.
// ---------------------------------------------------------------------------
#define BM 256
#define BN 128
#define BKH 64                          // halfs per stage-k (four k16 steps)
#define RSH 72                          // A / NT-B padded row stride (halfs)
#define RBH 136                         // NN-B padded row stride (halfs)
#define ATILE_BYTES (BM * RSH * 2)      // 36864
#define NSTAGE 3
#define SMEM_MAX (NSTAGE * (ATILE_BYTES + 128 * RSH * 2))   // 165888 (TRB variant)

template<typename Tout, bool TRB>
__global__ __launch_bounds__(256, 1)
void h_gemm(const __half* __restrict__ Ag, const __half* __restrict__ Bg,
            Tout* __restrict__ Cg, int K,
            long lda, long ldb, long ldc,
            long sAb, long sAh, long sBb, long sBh, long sCb, long sCh,
            int Hdiv, float alpha, const float* __restrict__ bias)
{
    constexpr uint32_t BTILE_BYTES = TRB ? (128 * RSH * 2) : (64 * RBH * 2);
    constexpr uint32_t STAGE_BYTES = ATILE_BYTES + BTILE_BYTES;

    extern __shared__ __half smem[];
    const uint32_t sbase = smem_u32(smem);

    const int tid  = threadIdx.x;
    const int wid  = tid >> 5;
    const int lane = tid & 31;
    const int wm   = wid >> 1;         // 0..3 -> 64-row slab
    const int wn   = wid & 1;          // 0..1 -> 64-col slab
    const int lg   = lane >> 2;        // 0..7
    const int lr   = lane & 3;         // 0..3

    const int zb = blockIdx.z / Hdiv;
    const int zh = blockIdx.z % Hdiv;
    const __half* A = Ag + zb * sAb + zh * sAh;
    const __half* B = Bg + zb * sBb + zh * sBh;
    Tout*         C = Cg + zb * sCb + zh * sCh;

    const int m0 = blockIdx.y * BM;
    const int n0 = blockIdx.x * BN;

    // A ldmatrix base (per-lane byte offset within a stage)
    const int arow = lane & 15;
    const int acol = (lane >> 4) << 3;
    const uint32_t aoff = ((wm * 64 + arow) * RSH + acol) * 2;

    // B ldmatrix base
    uint32_t boff;
    if constexpr (TRB) {
        const int brow = (lane & 7) | ((lane >> 4) << 3);
        const int bcol = ((lane >> 3) & 1) << 3;
        boff = ATILE_BYTES + ((wn * 64 + brow) * RSH + bcol) * 2;
    } else {
        const int krow = (lane & 7) + 8 * ((lane >> 3) & 1);
        const int ncol = wn * 64 + 8 * (lane >> 4);
        boff = ATILE_BYTES + krow * (RBH * 2) + ncol * 2;
    }

    float acc[4][8][4];
#pragma unroll
    for (int i = 0; i < 4; ++i)
#pragma unroll
        for (int j = 0; j < 8; ++j)
#pragma unroll
            for (int l = 0; l < 4; ++l) acc[i][j][l] = 0.f;

    const int NT = K / BKH;

    // one quarter of a stage load (j=0..3): A 2 chunks + B 1 chunk per thread
    auto cp_chunk = [&](int kt, int j) {
        const int ring = kt % NSTAGE;
        const uint32_t base = sbase + ring * STAGE_BYTES;
        const int k0 = kt * BKH;
#pragma unroll
        for (int i = 2 * j; i < 2 * j + 2; ++i) {
            int id = tid + i * 256;
            int row = id >> 3, ch = id & 7;
            CP_ASYNC16(base + row * (RSH * 2) + ch * 16,
                       A + (size_t)(m0 + row) * lda + k0 + ch * 8);
        }
        if constexpr (TRB) {
            int id = tid + j * 256;
            int row = id >> 3, ch = id & 7;
            CP_ASYNC16(base + ATILE_BYTES + row * (RSH * 2) + ch * 16,
                       B + (size_t)(n0 + row) * ldb + k0 + ch * 8);
        } else {
            int id = tid + j * 256;
            int row = id >> 4, ch = id & 15;
            CP_ASYNC16(base + ATILE_BYTES + row * (RBH * 2) + ch * 16,
                       B + (size_t)(k0 + row) * ldb + n0 + ch * 8);
        }
    };

    auto load_stage = [&](int kt) {
#pragma unroll
        for (int j = 0; j < 4; ++j) cp_chunk(kt, j);
        CP_COMMIT();
    };

    // fragment loader: frags for k16-chunk ks (0..3) of the stage at 'stg'
    auto ldm_all = [&](uint32_t stg, int ks, uint32_t af[4][4], uint32_t bf[8][2]) {
#pragma unroll
        for (int mt = 0; mt < 4; ++mt)
            ldm_x4(af[mt][0], af[mt][1], af[mt][2], af[mt][3],
                   stg + aoff + mt * (16 * RSH * 2) + ks * 32);
        if constexpr (TRB) {
#pragma unroll
            for (int np = 0; np < 4; ++np)
                ldm_x4(bf[2 * np][0], bf[2 * np][1], bf[2 * np + 1][0], bf[2 * np + 1][1],
                       stg + boff + np * (16 * RSH * 2) + ks * 32);
        } else {
#pragma unroll
            for (int np = 0; np < 4; ++np)
                ldm_x4_t(bf[2 * np][0], bf[2 * np][1], bf[2 * np + 1][0], bf[2 * np + 1][1],
                         stg + boff + ks * (16 * RBH * 2) + np * 32);
        }
    };

    // one quarter of an mma phase: fixed mt row, all 8 nt (8 HMMA)
    auto mma_quarter = [&](uint32_t af[4][4], uint32_t bf[8][2], int mt) {
#pragma unroll
        for (int nt = 0; nt < 8; ++nt)
            mma_f16(acc[mt][nt][0], acc[mt][nt][1], acc[mt][nt][2], acc[mt][nt][3],
                    af[mt][0], af[mt][1], af[mt][2], af[mt][3],
                    bf[nt][0], bf[nt][1]);
    };

    auto mma_all = [&](uint32_t af[4][4], uint32_t bf[8][2]) {
#pragma unroll
        for (int mt = 0; mt < 4; ++mt) mma_quarter(af, bf, mt);
    };

    load_stage(0); load_stage(1);

    // Prologue: stage 0 complete + published; preload (kt=0, ks=0) frags.
    CP_WAIT1();
    __syncthreads();

    uint32_t afA[4][4], bfA[8][2], afB[4][4], bfB[8][2];
    ldm_all(sbase, 0, afA, bfA);

    for (int kt = 0; kt < NT; ++kt) {
        const uint32_t stg = sbase + (kt % NSTAGE) * STAGE_BYTES;
        const bool doLoad = (kt + 2 < NT);

        // phase ks0 with interleaved cp.async for stage kt+2
        ldm_all(stg, 1, afB, bfB);
        mma_quarter(afA, bfA, 0);  if (doLoad) cp_chunk(kt + 2, 0);
        mma_quarter(afA, bfA, 1);  if (doLoad) cp_chunk(kt + 2, 1);
        mma_quarter(afA, bfA, 2);  if (doLoad) cp_chunk(kt + 2, 2);
        mma_quarter(afA, bfA, 3);  if (doLoad) cp_chunk(kt + 2, 3);
        CP_COMMIT();   // exactly one group per body (keeps wait_group math)

        // phase ks1
        ldm_all(stg, 2, afA, bfA);
        mma_all(afB, bfB);

        // phase ks2
        ldm_all(stg, 3, afB, bfB);
        mma_all(afA, bfA);

        // stage kt+1 complete + published before prefetching from it
        CP_WAIT1();
        __syncthreads();

        // phase ks3 + cross-iteration prefetch of (kt+1, ks0)
        const int ktn = (kt + 1 < NT) ? kt + 1 : kt;
        ldm_all(sbase + (ktn % NSTAGE) * STAGE_BYTES, 0, afA, bfA);
        mma_all(afB, bfB);
    }

    // epilogue
#pragma unroll
    for (int mt = 0; mt < 4; ++mt) {
#pragma unroll
        for (int nt = 0; nt < 8; ++nt) {
            const int r0 = m0 + wm * 64 + mt * 16 + lg;
            const int c0 = n0 + wn * 64 + nt * 8 + 2 * lr;
            float b0v = 0.f, b1v = 0.f;
            if (bias) { b0v = bias[c0]; b1v = bias[c0 + 1]; }
            float v00 = alpha * acc[mt][nt][0] + b0v;
            float v01 = alpha * acc[mt][nt][1] + b1v;
            float v10 = alpha * acc[mt][nt][2] + b0v;
            float v11 = alpha * acc[mt][nt][3] + b1v;
            if constexpr (sizeof(Tout) == 4) {
                *(float2*)((float*)C + (size_t)r0 * ldc + c0)       = make_float2(v00, v01);
                *(float2*)((float*)C + (size_t)(r0 + 8) * ldc + c0) = make_float2(v10, v11);
            } else {
                *(__half2*)((__half*)C + (size_t)r0 * ldc + c0)       = __float22half2_rn(make_float2(v00, v01));
                *(__half2*)((__half*)C + (size_t)(r0 + 8) * ldc + c0) = __float22half2_rn(make_float2(v10, v11));
            }
        }
    }
}

// fp32 -> fp16 elementwise (vectorized x2)
__global__ void conv_h(const float* __restrict__ in, __half* __restrict__ out, int n2)
{
    int i = blockIdx.x * blockDim.x + threadIdx.x;
    if (i < n2) {
        float2 v = *(const float2*)(in + 2 * i);
        *(__half2*)(out + 2 * i) = __float22half2_rn(v);
    }
}

// ---------------------------------------------------------------------------
// Row softmax in place on fp16 logits. 256 thr, 2048 cols.
// ---------------------------------------------------------------------------
__global__ void softmax_rows(__half* __restrict__ P)
{
    __half* q = P + (size_t)blockIdx.x * SEQ;
    const int tid = threadIdx.x;

    float2 v[4];
    float mx = -1e30f;
#pragma unroll
    for (int i = 0; i < 4; ++i) {
        v[i] = __half22float2(*(const __half2*)(q + 2 * tid + 512 * i));
        mx = fmaxf(mx, fmaxf(v[i].x, v[i].y));
    }
    __shared__ float red[256];
    red[tid] = mx; __syncthreads();
    for (int s = 128; s > 0; s >>= 1) { if (tid < s) red[tid] = fmaxf(red[tid], red[tid + s]); __syncthreads(); }
    mx = red[0]; __syncthreads();
    float sum = 0.f;
#pragma unroll
    for (int i = 0; i < 4; ++i) {
        v[i].x = __expf(v[i].x - mx); v[i].y = __expf(v[i].y - mx);
        sum += v[i].x + v[i].y;
    }
    red[tid] = sum; __syncthreads();
    for (int s = 128; s > 0; s >>= 1) { if (tid < s) red[tid] += red[tid + s]; __syncthreads(); }
    const float inv = 1.f / red[0];
#pragma unroll
    for (int i = 0; i < 4; ++i)
        *(__half2*)(q + 2 * tid + 512 * i) =
            __float22half2_rn(make_float2(v[i].x * inv, v[i].y * inv));
}

// ---------------------------------------------------------------------------
// Launch — s1 joins capture at t=0; K-proj runs on s1 concurrently with
// Q-proj on main (independent 1024-CTA grids pool into one 2048-CTA wave
// set). Fork after scores gates the V projection (co-runs with softmax);
// join before AV. All cross-stream edges originate inside the capture.
// ---------------------------------------------------------------------------
extern "C" void kernel_launch(void* const* d_in, const int* in_sizes, int n_in,
                              void* d_out, int out_size)
{
    const float* x  = (const float*)d_in[0];
    const float* Wq = (const float*)d_in[1];
    const float* bq = (const float*)d_in[2];
    const float* Wk = (const float*)d_in[3];
    const float* bk = (const float*)d_in[4];
    const float* Wv = (const float*)d_in[5];
    const float* bv = (const float*)d_in[6];
    const float* Wo = (const float*)d_in[7];
    const float* bo = (const float*)d_in[8];
    float* out = (float*)d_out;

    __half *pXh, *pQh, *pKh, *pVh, *pPh, *pAOh, *pWqh, *pWkh, *pWvh, *pWoh;
    cudaGetSymbolAddress((void**)&pXh,  g_Xh);
    cudaGetSymbolAddress((void**)&pQh,  g_Qh);
    cudaGetSymbolAddress((void**)&pKh,  g_Kh);
    cudaGetSymbolAddress((void**)&pVh,  g_Vh);
    cudaGetSymbolAddress((void**)&pPh,  g_Ph);
    cudaGetSymbolAddress((void**)&pAOh, g_AOh);
    cudaGetSymbolAddress((void**)&pWqh, g_Wqh);
    cudaGetSymbolAddress((void**)&pWkh, g_Wkh);
    cudaGetSymbolAddress((void**)&pWvh, g_Wvh);
    cudaGetSymbolAddress((void**)&pWoh, g_Woh);

    cudaFuncSetAttribute((const void*)h_gemm<__half, false>, cudaFuncAttributeMaxDynamicSharedMemorySize, SMEM_MAX);
    cudaFuncSetAttribute((const void*)h_gemm<__half, true>,  cudaFuncAttributeMaxDynamicSharedMemorySize, SMEM_MAX);
    cudaFuncSetAttribute((const void*)h_gemm<float, false>,  cudaFuncAttributeMaxDynamicSharedMemorySize, SMEM_MAX);

    // Side stream + events (host objects, created once; no device memory).
    static cudaStream_t s1 = nullptr;
    static cudaEvent_t evStart = nullptr, evX = nullptr, evKp = nullptr,
                       evFork = nullptr, evJoin = nullptr;
    if (s1 == nullptr) {
        cudaStreamCreateWithFlags(&s1, cudaStreamNonBlocking);
        cudaEventCreateWithFlags(&evStart, cudaEventDisableTiming);
        cudaEventCreateWithFlags(&evX,     cudaEventDisableTiming);
        cudaEventCreateWithFlags(&evKp,    cudaEventDisableTiming);
        cudaEventCreateWithFlags(&evFork,  cudaEventDisableTiming);
        cudaEventCreateWithFlags(&evJoin,  cudaEventDisableTiming);
    }

    const float scale = 1.0f / sqrtf((float)EMBD);

    // t=0: fork s1 into the capture FIRST.
    cudaEventRecord(evStart, 0);
    cudaStreamWaitEvent(s1, evStart, 0);

    // main: x convert (record evX), Wq convert, then Q projection.
    conv_h<<<(MROWS * EMBD / 2 + 255) / 256, 256>>>(x, pXh, MROWS * EMBD / 2);
    cudaEventRecord(evX, 0);
    conv_h<<<(EMBD * HE / 2 + 255) / 256, 256>>>(Wq, pWqh, EMBD * HE / 2);

    // s1: Wk convert, wait x, K projection (co-runs with Q-proj on main),
    // then Wv/Wo converts (fill idle HBM during tensor-bound phases).
    conv_h<<<(EMBD * HE / 2 + 255) / 256, 256, 0, s1>>>(Wk, pWkh, EMBD * HE / 2);
    cudaStreamWaitEvent(s1, evX, 0);
    {
        dim3 g(HE / BN, MROWS / BM, 1);
        h_gemm<__half, false><<<g, 256, SMEM_MAX, s1>>>(pXh, pWkh, pKh, EMBD, EMBD, HE, HE,
                                                        0, 0, 0, 0, 0, 0, 1, 1.f, bk);
    }
    cudaEventRecord(evKp, s1);
    conv_h<<<(EMBD * HE / 2 + 255) / 256, 256, 0, s1>>>(Wv, pWvh, EMBD * HE / 2);
    conv_h<<<(HE * EMBD / 2 + 255) / 256, 256, 0, s1>>>(Wo, pWoh, HE * EMBD / 2);

    // main: Q projection (x + Wq in main order), co-runs with K-proj on s1.
    {
        dim3 g(HE / BN, MROWS / BM, 1);
        h_gemm<__half, false><<<g, 256, SMEM_MAX>>>(pXh, pWqh, pQh, EMBD, EMBD, HE, HE,
                                                    0, 0, 0, 0, 0, 0, 1, 1.f, bq);
    }

    // scores needs Q (main order) + K (evKp).
    cudaStreamWaitEvent(0, evKp, 0);
    {
        dim3 g(SEQ / BN, SEQ / BM, BATCHN * HEADS);
        h_gemm<__half, true><<<g, 256, SMEM_MAX>>>(pQh, pKh, pPh, EMBD, HE, HE, SEQ,
                                                   (long)SEQ * HE, (long)EMBD,
                                                   (long)SEQ * HE, (long)EMBD,
                                                   (long)HEADS * SEQ * SEQ, (long)SEQ * SEQ,
                                                   HEADS, scale, nullptr);
    }

    // Fork AFTER scores: V-proj (side) co-runs with softmax (main).
    cudaEventRecord(evFork, 0);
    cudaStreamWaitEvent(s1, evFork, 0);

    // side stream: V projection (Wv converted earlier on s1, in order)
    {
        dim3 g(HE / BN, MROWS / BM, 1);
        h_gemm<__half, false><<<g, 256, SMEM_MAX, s1>>>(pXh, pWvh, pVh, EMBD, EMBD, HE, HE,
                                                        0, 0, 0, 0, 0, 0, 1, 1.f, bv);
    }
    cudaEventRecord(evJoin, s1);

    // main stream: softmax in place (fp16), concurrent with V projection
    softmax_rows<<<BATCHN * HEADS * SEQ, 256>>>(pPh);

    // join before AV
    cudaStreamWaitEvent(0, evJoin, 0);

    // 4) AO = P @ V (NN: B = V [s x emb] per head)
    {
        dim3 g(EMBD / BN, SEQ / BM, BATCHN * HEADS);
        h_gemm<__half, false><<<g, 256, SMEM_MAX>>>(pPh, pVh, pAOh, SEQ, SEQ, HE, HE,
                                                    (long)HEADS * SEQ * SEQ, (long)SEQ * SEQ,
                                                    (long)SEQ * HE, (long)EMBD,
                                                    (long)SEQ * HE, (long)EMBD,
                                                    HEADS, 1.f, nullptr);
    }

    // 5) out = AO @ Wo + bo (NN: B = Wo [4096 x 512])
    {
        dim3 g(EMBD / BN, MROWS / BM, 1);
        h_gemm<float, false><<<g, 256, SMEM_MAX>>>(pAOh, pWoh, out, HE, HE, EMBD, EMBD,
                                                   0, 0, 0, 0, 0, 0, 1, 1.f, bo);
    }
}